// round 5
// baseline (speedup 1.0000x reference)
#include <cuda_runtime.h>
#include <cuda_fp16.h>

#define BB    16
#define NN    65536
#define CC    256
#define DINN  16
#define DOUTT 16

__device__ __align__(16) __half g_s[DINN * BB * CC];      // s: [i][b][k], fp16
__device__ __align__(16) float  g_wdt[CC * DOUTT * DINN]; // w_diag: [c][o][i]
__device__ __align__(16) float  g_off[BB * CC * DOUTT];   // off: [b][c][o]

__device__ __forceinline__ float4 shfl_xor_f4(float4 v, int m) {
    v.x = __shfl_xor_sync(0xffffffffu, v.x, m);
    v.y = __shfl_xor_sync(0xffffffffu, v.y, m);
    v.z = __shfl_xor_sync(0xffffffffu, v.z, m);
    v.w = __shfl_xor_sync(0xffffffffu, v.w, m);
    return v;
}
__device__ __forceinline__ float dot4(float4 a, float4 b) {
    return a.x*b.x + a.y*b.y + a.z*b.z + a.w*b.w;
}

// ---------------------------------------------------------------------------
// kT: transpose w_diag [o][i][c] -> [c][o*16+i]
// ---------------------------------------------------------------------------
__global__ __launch_bounds__(256) void kT(const float* __restrict__ wdiag) {
    int idx = blockIdx.x * 256 + threadIdx.x;
    int c  = idx & 255;
    int oi = idx >> 8;
    g_wdt[c * 256 + oi] = wdiag[idx];
}

// ---------------------------------------------------------------------------
// kA: s[i][b][k=c] = sum_r x[b, pid[c*256+r], i]
// grid (C, 8): block handles b = {2y, 2y+1}; warps 0-3 -> b0, 4-7 -> b1.
// ids loaded once for both batches.
// ---------------------------------------------------------------------------
__global__ __launch_bounds__(256) void kA(const float* __restrict__ x,
                                          const int* __restrict__ pid) {
    int c = blockIdx.x;
    int t = threadIdx.x;
    int half = t >> 7;                 // 0 or 1
    int b = 2 * blockIdx.y + half;
    int tl = t & 127;
    int q = tl & 3, g = tl >> 2;       // g in 0..31
    int warp = t >> 5, lane = t & 31;

    __shared__ int ids[256];
    __shared__ float4 red[8][4];
    ids[t] = pid[c * 256 + t];
    __syncthreads();

    const float* xb = x + (size_t)b * NN * DINN;
    float4 acc = make_float4(0.f, 0.f, 0.f, 0.f);
#pragma unroll
    for (int j = 0; j < 8; j++) {
        int n = ids[g + 32 * j];
        float4 v = ((const float4*)(xb + (size_t)n * DINN))[q];
        acc.x += v.x; acc.y += v.y; acc.z += v.z; acc.w += v.w;
    }
#pragma unroll
    for (int m = 4; m < 32; m <<= 1) {
        float4 o = shfl_xor_f4(acc, m);
        acc.x += o.x; acc.y += o.y; acc.z += o.z; acc.w += o.w;
    }
    if (lane < 4) red[warp][lane] = acc;
    __syncthreads();
    if (t < 8) {
        int qq = t & 3, h = t >> 2;
        float4 v0 = red[4*h+0][qq], v1 = red[4*h+1][qq];
        float4 v2 = red[4*h+2][qq], v3 = red[4*h+3][qq];
        float4 v = make_float4(v0.x+v1.x+v2.x+v3.x, v0.y+v1.y+v2.y+v3.y,
                               v0.z+v1.z+v2.z+v3.z, v0.w+v1.w+v2.w+v3.w);
        int bb = 2 * blockIdx.y + h;
        int i0 = 4 * qq;
        g_s[((i0 + 0) * BB + bb) * CC + c] = __float2half(v.x);
        g_s[((i0 + 1) * BB + bb) * CC + c] = __float2half(v.y);
        g_s[((i0 + 2) * BB + bb) * CC + c] = __float2half(v.z);
        g_s[((i0 + 3) * BB + bb) * CC + c] = __float2half(v.w);
    }
}

// ---------------------------------------------------------------------------
// kB: off[b][c][o] = (1/N)*sum_{i,k} w_off[o][i][c][k]*s[b][k][i]
// grid C, 256 thr (8 warps); warp w -> o = {2w, 2w+1}.
// i-slice of s staged in smem; float4 weight loads, LDS.64 s reads, HFMA2.
// ---------------------------------------------------------------------------
__global__ __launch_bounds__(256) void kB(const float* __restrict__ woff) {
    int c    = blockIdx.x;
    int t    = threadIdx.x;
    int w    = t >> 5;
    int lane = t & 31;
    int o0 = 2 * w, o1 = o0 + 1;

    __shared__ __align__(16) __half2 sh[16 * 128];   // [b][h], h = k/2

    __half2 acc0[16], acc1[16];
#pragma unroll
    for (int b = 0; b < 16; b++) {
        acc0[b] = __float2half2_rn(0.f);
        acc1[b] = __float2half2_rn(0.f);
    }

    const uint4* gs4 = (const uint4*)g_s;

    for (int i = 0; i < 16; i++) {
        __syncthreads();
        for (int qq = t; qq < 512; qq += 256)
            ((uint4*)sh)[qq] = gs4[i * 512 + qq];
        __syncthreads();

        const float4* wb0 = (const float4*)(woff + (((size_t)o0 * 16 + i) * CC + c) * CC);
        const float4* wb1 = (const float4*)(woff + (((size_t)o1 * 16 + i) * CC + c) * CC);
#pragma unroll
        for (int s2 = 0; s2 < 2; s2++) {
            int j4 = s2 * 32 + lane;            // float4 index; covers k = 4*j4..4*j4+3
            float4 wf0 = wb0[j4];
            float4 wf1 = wb1[j4];
            __half2 w0lo = __floats2half2_rn(wf0.x, wf0.y);
            __half2 w0hi = __floats2half2_rn(wf0.z, wf0.w);
            __half2 w1lo = __floats2half2_rn(wf1.x, wf1.y);
            __half2 w1hi = __floats2half2_rn(wf1.z, wf1.w);
            int h = 2 * j4;
#pragma unroll
            for (int b = 0; b < 16; b++) {
                uint2 sp = *(const uint2*)&sh[b * 128 + h];   // LDS.64, stride 8B
                __half2 sa = *reinterpret_cast<__half2*>(&sp.x);
                __half2 sb = *reinterpret_cast<__half2*>(&sp.y);
                acc0[b] = __hfma2(w0lo, sa, acc0[b]);
                acc0[b] = __hfma2(w0hi, sb, acc0[b]);
                acc1[b] = __hfma2(w1lo, sa, acc1[b]);
                acc1[b] = __hfma2(w1hi, sb, acc1[b]);
            }
        }
    }

    const float invN = 1.0f / (float)NN;
#pragma unroll
    for (int b = 0; b < 16; b++) {
        float f0 = __low2float(acc0[b]) + __high2float(acc0[b]);
        float f1 = __low2float(acc1[b]) + __high2float(acc1[b]);
#pragma unroll
        for (int off = 16; off > 0; off >>= 1) {
            f0 += __shfl_xor_sync(0xffffffffu, f0, off);
            f1 += __shfl_xor_sync(0xffffffffu, f1, off);
        }
        if (lane == 0) {
            g_off[((size_t)b * CC + c) * DOUTT + o0] = f0 * invN;
            g_off[((size_t)b * CC + c) * DOUTT + o1] = f1 * invN;
        }
    }
}

// ---------------------------------------------------------------------------
// kC: grid (C, 4): block handles b = 4y..4y+3 (one per warp-pair).
// 4 lanes per row; other quarters via shfl_xor; weights in regs (q^p order),
// reused across all 4 batches' worth of work in the block via ids smem.
// ---------------------------------------------------------------------------
__global__ __launch_bounds__(256, 3) void kC(const float* __restrict__ x,
                                             const int* __restrict__ pid,
                                             const float* __restrict__ b1,
                                             float* __restrict__ out) {
    int c = blockIdx.x;
    int t = threadIdx.x;
    int half = t >> 6;                 // 0..3
    int b = 4 * blockIdx.y + half;
    int tl = t & 63;
    int q = tl & 3, g = tl >> 2;       // g in 0..15

    __shared__ int ids[256];
    ids[t] = pid[c * 256 + t];

    float4 wreg[4][4];
    float  bs[4];
    const float* wc = g_wdt + c * 256;
#pragma unroll
    for (int oo = 0; oo < 4; oo++) {
        int o = 4 * q + oo;
        bs[oo] = __ldg(&g_off[((size_t)b * CC + c) * DOUTT + o]) + __ldg(b1 + o);
#pragma unroll
        for (int p = 0; p < 4; p++)
            wreg[oo][p] = *(const float4*)(wc + o * 16 + 4 * (q ^ p));
    }
    __syncthreads();

    const float* xb = x + (size_t)b * NN * DINN;
    float* ob = out + (size_t)b * NN * DOUTT;

#pragma unroll 4
    for (int j = 0; j < 16; j++) {
        int n = ids[g + 16 * j];
        float4 X0 = ((const float4*)(xb + (size_t)n * DINN))[q];
        float4 X1 = shfl_xor_f4(X0, 1);
        float4 X2 = shfl_xor_f4(X0, 2);
        float4 X3 = shfl_xor_f4(X0, 3);

        float r0 = bs[0], r1 = bs[1], r2 = bs[2], r3 = bs[3];
        r0 += dot4(wreg[0][0], X0) + dot4(wreg[0][1], X1) + dot4(wreg[0][2], X2) + dot4(wreg[0][3], X3);
        r1 += dot4(wreg[1][0], X0) + dot4(wreg[1][1], X1) + dot4(wreg[1][2], X2) + dot4(wreg[1][3], X3);
        r2 += dot4(wreg[2][0], X0) + dot4(wreg[2][1], X1) + dot4(wreg[2][2], X2) + dot4(wreg[2][3], X3);
        r3 += dot4(wreg[3][0], X0) + dot4(wreg[3][1], X1) + dot4(wreg[3][2], X2) + dot4(wreg[3][3], X3);

        ((float4*)(ob + (size_t)n * DOUTT))[q] = make_float4(r0, r1, r2, r3);
    }
}

extern "C" void kernel_launch(void* const* d_in, const int* in_sizes, int n_in,
                              void* d_out, int out_size) {
    const float* x     = (const float*)d_in[0];
    const float* wdiag = (const float*)d_in[1];
    const float* woff  = (const float*)d_in[2];
    const float* b1    = (const float*)d_in[3];
    const int*   pid   = (const int*)d_in[4];
    float* out = (float*)d_out;

    kT<<<256, 256>>>(wdiag);
    kA<<<dim3(CC, 8), 256>>>(x, pid);
    kB<<<CC, 256>>>(woff);
    kC<<<dim3(CC, 4), 256>>>(x, pid, b1, out);
}

// round 6
// speedup vs baseline: 1.4209x; 1.4209x over previous
#include <cuda_runtime.h>
#include <cuda_fp16.h>

#define BB    16
#define NN    65536
#define CC    256
#define DINN  16
#define DOUTT 16

__device__ __align__(16) __half g_s[DINN * BB * CC];      // s: [i][b][k], fp16
__device__ __align__(16) float  g_wdt[CC * DOUTT * DINN]; // w_diag: [c][o][i]
__device__ __align__(16) float  g_off[BB * CC * DOUTT];   // off: [b][c][o]

__device__ __forceinline__ float4 shfl_xor_f4(float4 v, int m) {
    v.x = __shfl_xor_sync(0xffffffffu, v.x, m);
    v.y = __shfl_xor_sync(0xffffffffu, v.y, m);
    v.z = __shfl_xor_sync(0xffffffffu, v.z, m);
    v.w = __shfl_xor_sync(0xffffffffu, v.w, m);
    return v;
}
__device__ __forceinline__ float dot4(float4 a, float4 b) {
    return a.x*b.x + a.y*b.y + a.z*b.z + a.w*b.w;
}

// ---------------------------------------------------------------------------
// kT: transpose w_diag [o][i][c] -> [c][o*16+i]
// ---------------------------------------------------------------------------
__global__ __launch_bounds__(256) void kT(const float* __restrict__ wdiag) {
    int idx = blockIdx.x * 256 + threadIdx.x;
    int c  = idx & 255;
    int oi = idx >> 8;
    g_wdt[c * 256 + oi] = wdiag[idx];
}

// ---------------------------------------------------------------------------
// kA (R2 version): s[i][b][c] = sum_r x[b, pid[c*256+r], i]   (fp16 out)
// grid (C,B), 256 thr: q = t&3 (row quarter), g = t>>2 (64 groups x 4 rows).
// ---------------------------------------------------------------------------
__global__ __launch_bounds__(256) void kA(const float* __restrict__ x,
                                          const int* __restrict__ pid) {
    int c = blockIdx.x, b = blockIdx.y;
    __shared__ int ids[256];
    __shared__ float4 red[32];
    int t = threadIdx.x;
    int q = t & 3, g = t >> 2;
    int warp = t >> 5, lane = t & 31;
    ids[t] = pid[c * 256 + t];
    __syncthreads();

    const float* xb = x + (size_t)b * NN * DINN;
    float4 acc = make_float4(0.f, 0.f, 0.f, 0.f);
#pragma unroll
    for (int j = 0; j < 4; j++) {
        int n = ids[g + 64 * j];
        float4 v = ((const float4*)(xb + (size_t)n * DINN))[q];
        acc.x += v.x; acc.y += v.y; acc.z += v.z; acc.w += v.w;
    }
#pragma unroll
    for (int m = 4; m < 32; m <<= 1) {
        float4 o = shfl_xor_f4(acc, m);
        acc.x += o.x; acc.y += o.y; acc.z += o.z; acc.w += o.w;
    }
    if (lane < 4) red[warp * 4 + lane] = acc;
    __syncthreads();
    if (t < 32) {
        float4 v = red[t];
#pragma unroll
        for (int m = 4; m < 32; m <<= 1) {
            float4 o = shfl_xor_f4(v, m);
            v.x += o.x; v.y += o.y; v.z += o.z; v.w += o.w;
        }
        if (t < 4) {
            int i0 = 4 * t;
            g_s[((i0 + 0) * BB + b) * CC + c] = __float2half(v.x);
            g_s[((i0 + 1) * BB + b) * CC + c] = __float2half(v.y);
            g_s[((i0 + 2) * BB + b) * CC + c] = __float2half(v.z);
            g_s[((i0 + 3) * BB + b) * CC + c] = __float2half(v.w);
        }
    }
}

// ---------------------------------------------------------------------------
// kB (R2 version): off[b][c][o] = (1/N)*sum_{i,k} w_off[o][i][c][k]*s[b][k][i]
// grid C, 256 thr (8 warps); warp w -> o = {2w, 2w+1}; i-slice staged in smem.
// ---------------------------------------------------------------------------
__global__ __launch_bounds__(256) void kB(const float* __restrict__ woff) {
    int c    = blockIdx.x;
    int t    = threadIdx.x;
    int w    = t >> 5;
    int lane = t & 31;
    int o0 = 2 * w, o1 = o0 + 1;

    __shared__ __align__(16) __half2 sh[16 * 128];

    __half2 acc0[16], acc1[16];
#pragma unroll
    for (int b = 0; b < 16; b++) {
        acc0[b] = __float2half2_rn(0.f);
        acc1[b] = __float2half2_rn(0.f);
    }

    const uint4* gs4 = (const uint4*)g_s;

    for (int i = 0; i < 16; i++) {
        __syncthreads();
        for (int qq = t; qq < 512; qq += 256)
            ((uint4*)sh)[qq] = gs4[i * 512 + qq];
        __syncthreads();

        const float2* wb0 = (const float2*)(woff + (((size_t)o0 * 16 + i) * CC + c) * CC);
        const float2* wb1 = (const float2*)(woff + (((size_t)o1 * 16 + i) * CC + c) * CC);
#pragma unroll
        for (int stp = 0; stp < 4; stp++) {
            int h = stp * 32 + lane;
            float2 wf0 = wb0[h];
            float2 wf1 = wb1[h];
            __half2 wh0 = __floats2half2_rn(wf0.x, wf0.y);
            __half2 wh1 = __floats2half2_rn(wf1.x, wf1.y);
#pragma unroll
            for (int b = 0; b < 16; b++) {
                __half2 sv = sh[b * 128 + h];
                acc0[b] = __hfma2(wh0, sv, acc0[b]);
                acc1[b] = __hfma2(wh1, sv, acc1[b]);
            }
        }
    }

    const float invN = 1.0f / (float)NN;
#pragma unroll
    for (int b = 0; b < 16; b++) {
        float f0 = __low2float(acc0[b]) + __high2float(acc0[b]);
        float f1 = __low2float(acc1[b]) + __high2float(acc1[b]);
#pragma unroll
        for (int off = 16; off > 0; off >>= 1) {
            f0 += __shfl_xor_sync(0xffffffffu, f0, off);
            f1 += __shfl_xor_sync(0xffffffffu, f1, off);
        }
        if (lane == 0) {
            g_off[((size_t)b * CC + c) * DOUTT + o0] = f0 * invN;
            g_off[((size_t)b * CC + c) * DOUTT + o1] = f1 * invN;
        }
    }
}

// ---------------------------------------------------------------------------
// kC (R4 version, measured 32.3us): grid (C,B), 256 thr, sync-free prologue,
// 4 lanes/row, quarters via shfl_xor, weights in regs (q^p order), <=85 regs.
// ---------------------------------------------------------------------------
__global__ __launch_bounds__(256, 3) void kC(const float* __restrict__ x,
                                             const int* __restrict__ pid,
                                             const float* __restrict__ b1,
                                             float* __restrict__ out) {
    int c = blockIdx.x, b = blockIdx.y;
    int t = threadIdx.x;
    int q = t & 3, g = t >> 2;

    const int* pc = pid + c * 256;
    int ns[4];
    ns[0] = __ldg(pc + g);
    ns[1] = __ldg(pc + g + 64);
    ns[2] = __ldg(pc + g + 128);
    ns[3] = __ldg(pc + g + 192);

    float4 wreg[4][4];
    float  bs[4];
    const float* wc = g_wdt + c * 256;
#pragma unroll
    for (int oo = 0; oo < 4; oo++) {
        int o = 4 * q + oo;
        bs[oo] = __ldg(&g_off[((size_t)b * CC + c) * DOUTT + o]) + __ldg(b1 + o);
#pragma unroll
        for (int p = 0; p < 4; p++)
            wreg[oo][p] = *(const float4*)(wc + o * 16 + 4 * (q ^ p));
    }

    const float* xb = x + (size_t)b * NN * DINN;
    float* ob = out + (size_t)b * NN * DOUTT;

#pragma unroll
    for (int j = 0; j < 4; j++) {
        int n = ns[j];
        float4 X0 = ((const float4*)(xb + (size_t)n * DINN))[q];
        float4 X1 = shfl_xor_f4(X0, 1);
        float4 X2 = shfl_xor_f4(X0, 2);
        float4 X3 = shfl_xor_f4(X0, 3);

        float r0 = bs[0], r1 = bs[1], r2 = bs[2], r3 = bs[3];
        r0 += dot4(wreg[0][0], X0) + dot4(wreg[0][1], X1) + dot4(wreg[0][2], X2) + dot4(wreg[0][3], X3);
        r1 += dot4(wreg[1][0], X0) + dot4(wreg[1][1], X1) + dot4(wreg[1][2], X2) + dot4(wreg[1][3], X3);
        r2 += dot4(wreg[2][0], X0) + dot4(wreg[2][1], X1) + dot4(wreg[2][2], X2) + dot4(wreg[2][3], X3);
        r3 += dot4(wreg[3][0], X0) + dot4(wreg[3][1], X1) + dot4(wreg[3][2], X2) + dot4(wreg[3][3], X3);

        ((float4*)(ob + (size_t)n * DOUTT))[q] = make_float4(r0, r1, r2, r3);
    }
}

extern "C" void kernel_launch(void* const* d_in, const int* in_sizes, int n_in,
                              void* d_out, int out_size) {
    const float* x     = (const float*)d_in[0];
    const float* wdiag = (const float*)d_in[1];
    const float* woff  = (const float*)d_in[2];
    const float* b1    = (const float*)d_in[3];
    const int*   pid   = (const int*)d_in[4];
    float* out = (float*)d_out;

    kT<<<256, 256>>>(wdiag);
    kA<<<dim3(CC, BB), 256>>>(x, pid);
    kB<<<CC, 256>>>(woff);
    kC<<<dim3(CC, BB), 256>>>(x, pid, b1, out);
}